// round 15
// baseline (speedup 1.0000x reference)
#include <cuda_runtime.h>
#include <cuda_fp16.h>
#include <cstdint>
#include <cstddef>

// ---------------------------------------------------------------------------
// LoRALinear champion v4 — ONE persistent kernel:
//   Phase 1: grid-stride  X->fp16 RN  +  W' = NF4-dequant + LoRA fold
//   device-wide ticket barrier (replay-safe monotonic counter)
//   Phase 2: persistent tile loop running the R13 GEMM mainloop
//            (fp16 m16n8k16, fp32 accum, CTA 128x128xBK64, warp 64x32,
//             3-stage cp.async, 2 CTAs/SM)
// Eliminates the prep->GEMM launch seam and per-wave transitions.
// ---------------------------------------------------------------------------

#define IN_DIM   4096
#define OUT_DIM  4096
#define RANK_    16
#define M_MAX    8192
#define GRID_P   296           // 2 CTAs/SM x 148 SMs (resident on 148- and 152-SM parts)

__constant__ float c_nf4[16] = {
    -1.0f, -0.6961928009986877f, -0.5250730514526367f, -0.39491748809814453f,
    -0.28444138169288635f, -0.18477343022823334f, -0.09105003625154495f, 0.0f,
    0.07958029955625534f, 0.16093020141124725f, 0.24611230194568634f,
    0.33791524171829224f, 0.44070982933044434f, 0.5626170039176941f,
    0.7229568362236023f, 1.0f };

__device__ __half g_w[(size_t)OUT_DIM * IN_DIM];
__device__ __half g_x[(size_t)M_MAX * IN_DIM];
__device__ unsigned long long g_bar;      // monotonic ticket counter (never reset)

#define BM 128
#define BN 128
#define BK 64
#define LDS_H  72              // halves per smem row (144B rows, aligned, conflict-free)
#define STAGES 3
#define A_ST  (BM * LDS_H)
#define B_ST  (BN * LDS_H)

__device__ __forceinline__ unsigned smem_u32(const void* p) {
    return (unsigned)__cvta_generic_to_shared(p);
}

__global__ void __launch_bounds__(256, 2)
fused_persistent_kernel(const float* __restrict__ x,
                        const int* __restrict__ wq,
                        const float* __restrict__ scales,
                        const float* __restrict__ la,
                        const float* __restrict__ lb,
                        float* __restrict__ C, int M) {
    extern __shared__ __half sm[];
    __half* As = sm;
    __half* Bs = sm + STAGES * A_ST;

    const int tid = threadIdx.x;

    // ====================== Phase 1: prep (grid-stride) ======================
    {
        // X -> fp16 (RN), 8 elems per item
        const int n8 = (M * IN_DIM) / 8;
        for (int i = blockIdx.x * 256 + tid; i < n8; i += GRID_P * 256) {
            float4 v0 = reinterpret_cast<const float4*>(x)[2 * i];
            float4 v1 = reinterpret_cast<const float4*>(x)[2 * i + 1];
            __half2 h[4];
            h[0] = __floats2half2_rn(v0.x, v0.y);
            h[1] = __floats2half2_rn(v0.z, v0.w);
            h[2] = __floats2half2_rn(v1.x, v1.y);
            h[3] = __floats2half2_rn(v1.z, v1.w);
            reinterpret_cast<uint4*>(g_x)[i] = *reinterpret_cast<uint4*>(h);
        }
        // W' = nf4[wq]*scale + 2*(B@A), fp16 RN; one float4-of-codes per item
        const int n4 = OUT_DIM * (IN_DIM / 4);
        for (int idx = blockIdx.x * 256 + tid; idx < n4; idx += GRID_P * 256) {
            int o  = idx >> 10;
            int i4 = idx & 1023;
            int4 c = reinterpret_cast<const int4*>(wq)[idx];
            float s = scales[o * (IN_DIM / 64) + (i4 >> 4)];

            float lx = 0.f, ly = 0.f, lz = 0.f, lw = 0.f;
            #pragma unroll
            for (int r = 0; r < RANK_; r++) {
                float bb = __ldg(&lb[o * RANK_ + r]);
                float4 av = reinterpret_cast<const float4*>(la)[r * (IN_DIM / 4) + i4];
                lx = fmaf(bb, av.x, lx); ly = fmaf(bb, av.y, ly);
                lz = fmaf(bb, av.z, lz); lw = fmaf(bb, av.w, lw);
            }
            __half2 h0 = __floats2half2_rn(fmaf(c_nf4[c.x], s, 2.0f * lx),
                                           fmaf(c_nf4[c.y], s, 2.0f * ly));
            __half2 h1 = __floats2half2_rn(fmaf(c_nf4[c.z], s, 2.0f * lz),
                                           fmaf(c_nf4[c.w], s, 2.0f * lw));
            uint2 u = make_uint2(*reinterpret_cast<uint32_t*>(&h0),
                                 *reinterpret_cast<uint32_t*>(&h1));
            reinterpret_cast<uint2*>(g_w)[idx] = u;
        }
    }

    // =================== device-wide ticket barrier (replay-safe) ===========
    __syncthreads();
    if (tid == 0) {
        __threadfence();   // publish phase-1 writes (gpu scope)
        unsigned long long old = atomicAdd(&g_bar, 1ULL);
        unsigned long long target = (old / GRID_P + 1ULL) * GRID_P;
        for (;;) {
            unsigned long long v;
            asm volatile("ld.global.acquire.gpu.u64 %0, [%1];"
                         : "=l"(v) : "l"(&g_bar) : "memory");
            if (v >= target) break;
            __nanosleep(128);
        }
    }
    __syncthreads();

    // ====================== Phase 2: persistent GEMM tiles ==================
    const int lane = tid & 31;
    const int w    = tid >> 5;
    const int wm   = (w & 1) * 64;          // warp tile 64(M) x 32(N)
    const int wn   = (w >> 1) * 32;
    const int g    = lane >> 2;
    const int tg   = lane & 3;

    const int a_row_off = (lane & 7) + ((lane >> 3) & 1) * 8;
    const int a_khalf   = (lane >> 4);
    const int b_row_off = ((lane >> 4) & 1) * 8 + (lane & 7);
    const int b_khalf   = (lane >> 3) & 1;

    const int KT      = IN_DIM / BK;        // 64
    const int n_tiles = (M / BM) * (OUT_DIM / BN);   // 2048

    for (int tile = blockIdx.x; tile < n_tiles; tile += GRID_P) {
        const int mtile = tile & 63;        // 64 consecutive tiles share ntile
        const int ntile = tile >> 6;

        const __half* Abase = g_x + (size_t)(mtile * BM) * IN_DIM;
        const __half* Bbase = g_w + (size_t)(ntile * BN) * IN_DIM;

        float acc[4][4][4];
        #pragma unroll
        for (int a = 0; a < 4; a++)
            #pragma unroll
            for (int b = 0; b < 4; b++)
                #pragma unroll
                for (int c = 0; c < 4; c++) acc[a][b][c] = 0.f;

        auto load_stage = [&](int buf, int kt) {
            unsigned abase = smem_u32(As + (size_t)buf * A_ST);
            unsigned bbase = smem_u32(Bs + (size_t)buf * B_ST);
            #pragma unroll
            for (int p = 0; p < 4; p++) {   // A: 128 rows x 8 chunks of 16B
                int cid = p * 256 + tid;
                int r = cid >> 3, c = cid & 7;
                unsigned dst = abase + (unsigned)((r * LDS_H + c * 8) * 2);
                const __half* src = Abase + (size_t)r * IN_DIM + kt * BK + c * 8;
                asm volatile("cp.async.cg.shared.global [%0], [%1], 16;\n"
                             :: "r"(dst), "l"(src));
            }
            #pragma unroll
            for (int p = 0; p < 4; p++) {   // B: 128 rows x 8 chunks of 16B
                int cid = p * 256 + tid;
                int r = cid >> 3, c = cid & 7;
                unsigned dst = bbase + (unsigned)((r * LDS_H + c * 8) * 2);
                const __half* src = Bbase + (size_t)r * IN_DIM + kt * BK + c * 8;
                asm volatile("cp.async.cg.shared.global [%0], [%1], 16;\n"
                             :: "r"(dst), "l"(src));
            }
        };

        load_stage(0, 0);
        asm volatile("cp.async.commit_group;\n");
        load_stage(1, 1);
        asm volatile("cp.async.commit_group;\n");

        int buf = 0;
        for (int kt = 0; kt < KT; kt++) {
            asm volatile("cp.async.wait_group 1;\n");
            __syncthreads();

            if (kt + 2 < KT) {
                int nb = buf + 2; if (nb >= STAGES) nb -= STAGES;
                load_stage(nb, kt + 2);
            }
            asm volatile("cp.async.commit_group;\n");

            unsigned abuf = smem_u32(As + (size_t)buf * A_ST);
            unsigned bbuf = smem_u32(Bs + (size_t)buf * B_ST);

            #pragma unroll
            for (int ks = 0; ks < 4; ks++) {
                uint32_t af[4][4], bf[2][4];
                #pragma unroll
                for (int mi = 0; mi < 4; mi++) {
                    unsigned addr = abuf + (unsigned)(((wm + mi * 16 + a_row_off) * LDS_H
                                                      + ks * 16 + a_khalf * 8) * 2);
                    asm volatile("ldmatrix.sync.aligned.m8n8.x4.shared.b16 "
                                 "{%0,%1,%2,%3}, [%4];"
                                 : "=r"(af[mi][0]), "=r"(af[mi][1]),
                                   "=r"(af[mi][2]), "=r"(af[mi][3]) : "r"(addr));
                }
                #pragma unroll
                for (int np = 0; np < 2; np++) {
                    unsigned addr = bbuf + (unsigned)(((wn + np * 16 + b_row_off) * LDS_H
                                                      + ks * 16 + b_khalf * 8) * 2);
                    asm volatile("ldmatrix.sync.aligned.m8n8.x4.shared.b16 "
                                 "{%0,%1,%2,%3}, [%4];"
                                 : "=r"(bf[np][0]), "=r"(bf[np][1]),
                                   "=r"(bf[np][2]), "=r"(bf[np][3]) : "r"(addr));
                }
                #pragma unroll
                for (int mi = 0; mi < 4; mi++)
                    #pragma unroll
                    for (int np = 0; np < 2; np++) {
                        asm volatile(
                            "mma.sync.aligned.m16n8k16.row.col.f32.f16.f16.f32 "
                            "{%0,%1,%2,%3}, {%4,%5,%6,%7}, {%8,%9}, {%0,%1,%2,%3};\n"
                            : "+f"(acc[mi][2*np][0]), "+f"(acc[mi][2*np][1]),
                              "+f"(acc[mi][2*np][2]), "+f"(acc[mi][2*np][3])
                            : "r"(af[mi][0]), "r"(af[mi][1]), "r"(af[mi][2]), "r"(af[mi][3]),
                              "r"(bf[np][0]), "r"(bf[np][1]));
                        asm volatile(
                            "mma.sync.aligned.m16n8k16.row.col.f32.f16.f16.f32 "
                            "{%0,%1,%2,%3}, {%4,%5,%6,%7}, {%8,%9}, {%0,%1,%2,%3};\n"
                            : "+f"(acc[mi][2*np+1][0]), "+f"(acc[mi][2*np+1][1]),
                              "+f"(acc[mi][2*np+1][2]), "+f"(acc[mi][2*np+1][3])
                            : "r"(af[mi][0]), "r"(af[mi][1]), "r"(af[mi][2]), "r"(af[mi][3]),
                              "r"(bf[np][2]), "r"(bf[np][3]));
                    }
            }
            if (++buf == STAGES) buf = 0;
        }

        // epilogue (registers only)
        #pragma unroll
        for (int mi = 0; mi < 4; mi++) {
            int row0 = mtile * BM + wm + mi * 16 + g;
            #pragma unroll
            for (int ni = 0; ni < 4; ni++) {
                int col = ntile * BN + wn + ni * 8 + tg * 2;
                float2 v0 = make_float2(acc[mi][ni][0], acc[mi][ni][1]);
                float2 v1 = make_float2(acc[mi][ni][2], acc[mi][ni][3]);
                *reinterpret_cast<float2*>(&C[(size_t)row0 * OUT_DIM + col])       = v0;
                *reinterpret_cast<float2*>(&C[(size_t)(row0 + 8) * OUT_DIM + col]) = v1;
            }
        }

        // fence smem reuse: next tile's prologue overwrites stages 0/1 which
        // lagging warps may still be reading in this tile's final kt.
        __syncthreads();
    }
}

// ---------------------------------------------------------------------------
// Launcher — single persistent launch
// ---------------------------------------------------------------------------
extern "C" void kernel_launch(void* const* d_in, const int* in_sizes, int n_in,
                              void* d_out, int out_size) {
    const float* x      = (const float*)d_in[0];
    const int*   wq     = (const int*)  d_in[1];
    const float* scales = (const float*)d_in[2];
    const float* la     = (const float*)d_in[3];
    const float* lb     = (const float*)d_in[4];
    float* out = (float*)d_out;

    int M = in_sizes[0] / IN_DIM;    // 8192

    const int smem_bytes = STAGES * (A_ST + B_ST) * (int)sizeof(__half); // 110592
    cudaFuncSetAttribute(fused_persistent_kernel,
                         cudaFuncAttributeMaxDynamicSharedMemorySize, smem_bytes);
    fused_persistent_kernel<<<GRID_P, 256, smem_bytes>>>(x, wq, scales, la, lb,
                                                         out, M);
}

// round 16
// speedup vs baseline: 1.1294x; 1.1294x over previous
#include <cuda_runtime.h>
#include <cuda_fp16.h>
#include <cstdint>
#include <cstddef>

// ---------------------------------------------------------------------------
// LoRALinear champion v5 (= R13 + warp-staggered ks schedule + streaming C):
//  - ONE prep kernel (branch): X->fp16 RN AND W' = NF4-dequant + LoRA fold (PDL)
//  - fp16 m16n8k16 GEMM, fp32 accum, CTA 128x128xBK64, warp tile 64x32,
//    3-stage cp.async, 2 CTAs/SM.
//  - Each warp walks the 4 k-slices in a rotated order (de-convoys the
//    post-barrier LDSM burst); C stores use .cs to protect B in L2.
// ---------------------------------------------------------------------------

#define IN_DIM   4096
#define OUT_DIM  4096
#define RANK_    16
#define M_MAX    8192

__constant__ float c_nf4[16] = {
    -1.0f, -0.6961928009986877f, -0.5250730514526367f, -0.39491748809814453f,
    -0.28444138169288635f, -0.18477343022823334f, -0.09105003625154495f, 0.0f,
    0.07958029955625534f, 0.16093020141124725f, 0.24611230194568634f,
    0.33791524171829224f, 0.44070982933044434f, 0.5626170039176941f,
    0.7229568362236023f, 1.0f };

__device__ __half g_w[(size_t)OUT_DIM * IN_DIM];
__device__ __half g_x[(size_t)M_MAX * IN_DIM];

// ---------------------------------------------------------------------------
// Prep kernel: blocks [0,nblk_x) round X; rest dequant+fold W'
// ---------------------------------------------------------------------------
__global__ void prep_kernel(const float* __restrict__ x, __half* __restrict__ xr,
                            int n8, int nblk_x,
                            const int* __restrict__ wq,
                            const float* __restrict__ scales,
                            const float* __restrict__ la,
                            const float* __restrict__ lb,
                            __half* __restrict__ W) {
    if (blockIdx.x < (unsigned)nblk_x) {
        int i = blockIdx.x * blockDim.x + threadIdx.x;
        if (i < n8) {
            float4 v0 = reinterpret_cast<const float4*>(x)[2 * i];
            float4 v1 = reinterpret_cast<const float4*>(x)[2 * i + 1];
            __half2 h[4];
            h[0] = __floats2half2_rn(v0.x, v0.y);
            h[1] = __floats2half2_rn(v0.z, v0.w);
            h[2] = __floats2half2_rn(v1.x, v1.y);
            h[3] = __floats2half2_rn(v1.z, v1.w);
            reinterpret_cast<uint4*>(xr)[i] = *reinterpret_cast<uint4*>(h);
        }
    } else {
        __shared__ float cb[16];
        if (threadIdx.x < 16) cb[threadIdx.x] = c_nf4[threadIdx.x];
        __syncthreads();

        int idx = (blockIdx.x - nblk_x) * blockDim.x + threadIdx.x;
        const int n4 = OUT_DIM * (IN_DIM / 4);
        if (idx < n4) {
            int o  = idx >> 10;
            int i4 = idx & 1023;

            int4 c = reinterpret_cast<const int4*>(wq)[idx];
            float s = scales[o * (IN_DIM / 64) + (i4 >> 4)];

            float lx = 0.f, ly = 0.f, lz = 0.f, lw = 0.f;
            #pragma unroll
            for (int r = 0; r < RANK_; r++) {
                float bb = __ldg(&lb[o * RANK_ + r]);
                float4 av = reinterpret_cast<const float4*>(la)[r * (IN_DIM / 4) + i4];
                lx = fmaf(bb, av.x, lx); ly = fmaf(bb, av.y, ly);
                lz = fmaf(bb, av.z, lz); lw = fmaf(bb, av.w, lw);
            }

            __half2 h0 = __floats2half2_rn(fmaf(cb[c.x], s, 2.0f * lx),
                                           fmaf(cb[c.y], s, 2.0f * ly));
            __half2 h1 = __floats2half2_rn(fmaf(cb[c.z], s, 2.0f * lz),
                                           fmaf(cb[c.w], s, 2.0f * lw));
            uint2 u = make_uint2(*reinterpret_cast<uint32_t*>(&h0),
                                 *reinterpret_cast<uint32_t*>(&h1));
            reinterpret_cast<uint2*>(W)[idx] = u;
        }
    }
#if __CUDA_ARCH__ >= 900
    cudaTriggerProgrammaticLaunchCompletion();
#endif
}

// ---------------------------------------------------------------------------
// GEMM: fp16 m16n8k16, CTA 128x128x64, 8 warps 2(M)x4(N), warp tile 64x32.
// 3-stage cp.async (2 in flight), 2 CTAs/SM. Warp-rotated ks order.
// ---------------------------------------------------------------------------
#define BM 128
#define BN 128
#define BK 64
#define LDS_H  72
#define STAGES 3
#define A_ST  (BM * LDS_H)
#define B_ST  (BN * LDS_H)

__device__ __forceinline__ unsigned smem_u32(const void* p) {
    return (unsigned)__cvta_generic_to_shared(p);
}

__global__ void __launch_bounds__(256, 2)
gemm_fp16_kernel(const __half* __restrict__ A, const __half* __restrict__ B,
                 float* __restrict__ C, int M, int N, int K) {
    extern __shared__ __half sm[];
    __half* As = sm;
    __half* Bs = sm + STAGES * A_ST;

    const int tid  = threadIdx.x;
    const int lane = tid & 31;
    const int w    = tid >> 5;
    const int wm   = (w & 1) * 64;          // warp tile 64(M) x 32(N)
    const int wn   = (w >> 1) * 32;
    const int g    = lane >> 2;
    const int tg   = lane & 3;
    const int krot = w & 3;                 // per-warp ks rotation

    const int mtile = blockIdx.x & 63;      // 64 CTAs share one N-tile
    const int ntile = blockIdx.x >> 6;

    const int a_row_off = (lane & 7) + ((lane >> 3) & 1) * 8;
    const int a_khalf   = (lane >> 4);
    const int b_row_off = ((lane >> 4) & 1) * 8 + (lane & 7);
    const int b_khalf   = (lane >> 3) & 1;

    float acc[4][4][4];
    #pragma unroll
    for (int a = 0; a < 4; a++)
        #pragma unroll
        for (int b = 0; b < 4; b++)
            #pragma unroll
            for (int c = 0; c < 4; c++) acc[a][b][c] = 0.f;

    const int KT = K / BK;   // 64

    const __half* Abase = A + (size_t)(mtile * BM) * K;
    const __half* Bbase = B + (size_t)(ntile * BN) * K;

#if __CUDA_ARCH__ >= 900
    cudaGridDependencySynchronize();
#endif

    auto load_stage = [&](int buf, int kt) {
        unsigned abase = smem_u32(As + (size_t)buf * A_ST);
        unsigned bbase = smem_u32(Bs + (size_t)buf * B_ST);
        #pragma unroll
        for (int p = 0; p < 4; p++) {
            int cid = p * 256 + tid;
            int r = cid >> 3, c = cid & 7;
            unsigned dst = abase + (unsigned)((r * LDS_H + c * 8) * 2);
            const __half* src = Abase + (size_t)r * K + kt * BK + c * 8;
            asm volatile("cp.async.cg.shared.global [%0], [%1], 16;\n"
                         :: "r"(dst), "l"(src));
        }
        #pragma unroll
        for (int p = 0; p < 4; p++) {
            int cid = p * 256 + tid;
            int r = cid >> 3, c = cid & 7;
            unsigned dst = bbase + (unsigned)((r * LDS_H + c * 8) * 2);
            const __half* src = Bbase + (size_t)r * K + kt * BK + c * 8;
            asm volatile("cp.async.cg.shared.global [%0], [%1], 16;\n"
                         :: "r"(dst), "l"(src));
        }
    };

    load_stage(0, 0);
    asm volatile("cp.async.commit_group;\n");
    load_stage(1, 1);
    asm volatile("cp.async.commit_group;\n");

    int buf = 0;
    for (int kt = 0; kt < KT; kt++) {
        asm volatile("cp.async.wait_group 1;\n");
        __syncthreads();

        if (kt + 2 < KT) {
            int nb = buf + 2; if (nb >= STAGES) nb -= STAGES;
            load_stage(nb, kt + 2);
        }
        asm volatile("cp.async.commit_group;\n");

        unsigned abuf = smem_u32(As + (size_t)buf * A_ST);
        unsigned bbuf = smem_u32(Bs + (size_t)buf * B_ST);

        #pragma unroll
        for (int kss = 0; kss < 4; kss++) {
            const int ks = (kss + krot) & 3;   // warp-rotated slice order
            uint32_t af[4][4], bf[2][4];
            #pragma unroll
            for (int mi = 0; mi < 4; mi++) {
                unsigned addr = abuf + (unsigned)(((wm + mi * 16 + a_row_off) * LDS_H
                                                  + ks * 16 + a_khalf * 8) * 2);
                asm volatile("ldmatrix.sync.aligned.m8n8.x4.shared.b16 "
                             "{%0,%1,%2,%3}, [%4];"
                             : "=r"(af[mi][0]), "=r"(af[mi][1]),
                               "=r"(af[mi][2]), "=r"(af[mi][3]) : "r"(addr));
            }
            #pragma unroll
            for (int np = 0; np < 2; np++) {
                unsigned addr = bbuf + (unsigned)(((wn + np * 16 + b_row_off) * LDS_H
                                                  + ks * 16 + b_khalf * 8) * 2);
                asm volatile("ldmatrix.sync.aligned.m8n8.x4.shared.b16 "
                             "{%0,%1,%2,%3}, [%4];"
                             : "=r"(bf[np][0]), "=r"(bf[np][1]),
                               "=r"(bf[np][2]), "=r"(bf[np][3]) : "r"(addr));
            }
            #pragma unroll
            for (int mi = 0; mi < 4; mi++)
                #pragma unroll
                for (int np = 0; np < 2; np++) {
                    asm volatile(
                        "mma.sync.aligned.m16n8k16.row.col.f32.f16.f16.f32 "
                        "{%0,%1,%2,%3}, {%4,%5,%6,%7}, {%8,%9}, {%0,%1,%2,%3};\n"
                        : "+f"(acc[mi][2*np][0]), "+f"(acc[mi][2*np][1]),
                          "+f"(acc[mi][2*np][2]), "+f"(acc[mi][2*np][3])
                        : "r"(af[mi][0]), "r"(af[mi][1]), "r"(af[mi][2]), "r"(af[mi][3]),
                          "r"(bf[np][0]), "r"(bf[np][1]));
                    asm volatile(
                        "mma.sync.aligned.m16n8k16.row.col.f32.f16.f16.f32 "
                        "{%0,%1,%2,%3}, {%4,%5,%6,%7}, {%8,%9}, {%0,%1,%2,%3};\n"
                        : "+f"(acc[mi][2*np+1][0]), "+f"(acc[mi][2*np+1][1]),
                          "+f"(acc[mi][2*np+1][2]), "+f"(acc[mi][2*np+1][3])
                        : "r"(af[mi][0]), "r"(af[mi][1]), "r"(af[mi][2]), "r"(af[mi][3]),
                          "r"(bf[np][2]), "r"(bf[np][3]));
                }
        }
        if (++buf == STAGES) buf = 0;
    }

    // epilogue: streaming stores (don't evict B from L2)
    #pragma unroll
    for (int mi = 0; mi < 4; mi++) {
        int row0 = mtile * BM + wm + mi * 16 + g;
        #pragma unroll
        for (int ni = 0; ni < 4; ni++) {
            int col = ntile * BN + wn + ni * 8 + tg * 2;
            float2 v0 = make_float2(acc[mi][ni][0], acc[mi][ni][1]);
            float2 v1 = make_float2(acc[mi][ni][2], acc[mi][ni][3]);
            __stcs(reinterpret_cast<float2*>(&C[(size_t)row0 * N + col]), v0);
            __stcs(reinterpret_cast<float2*>(&C[(size_t)(row0 + 8) * N + col]), v1);
        }
    }
}

// ---------------------------------------------------------------------------
// Launcher
// ---------------------------------------------------------------------------
extern "C" void kernel_launch(void* const* d_in, const int* in_sizes, int n_in,
                              void* d_out, int out_size) {
    const float* x      = (const float*)d_in[0];
    const int*   wq     = (const int*)  d_in[1];
    const float* scales = (const float*)d_in[2];
    const float* la     = (const float*)d_in[3];
    const float* lb     = (const float*)d_in[4];
    float* out = (float*)d_out;

    int M = in_sizes[0] / IN_DIM;    // 8192

    __half *gw = nullptr, *gx = nullptr;
    cudaGetSymbolAddress((void**)&gw, g_w);
    cudaGetSymbolAddress((void**)&gx, g_x);

    int n8x    = (M * IN_DIM) / 8;
    int nblk_x = (n8x + 255) / 256;
    int n4w    = OUT_DIM * (IN_DIM / 4);
    int nblk_w = (n4w + 255) / 256;
    prep_kernel<<<nblk_x + nblk_w, 256>>>(x, gx, n8x, nblk_x,
                                          wq, scales, la, lb, gw);

    const int smem_bytes = STAGES * (A_ST + B_ST) * (int)sizeof(__half); // 110592
    cudaFuncSetAttribute(gemm_fp16_kernel,
                         cudaFuncAttributeMaxDynamicSharedMemorySize, smem_bytes);
    int grid = (M / BM) * (OUT_DIM / BN);   // 2048

    cudaLaunchConfig_t cfg = {};
    cfg.gridDim  = dim3(grid, 1, 1);
    cfg.blockDim = dim3(256, 1, 1);
    cfg.dynamicSmemBytes = smem_bytes;
    cudaLaunchAttribute attrs[1];
    attrs[0].id = cudaLaunchAttributeProgrammaticStreamSerialization;
    attrs[0].val.programmaticStreamSerializationAllowed = 1;
    cfg.attrs = attrs;
    cfg.numAttrs = 1;
    cudaError_t e = cudaLaunchKernelEx(&cfg, gemm_fp16_kernel,
                                       (const __half*)gx, (const __half*)gw,
                                       out, M, OUT_DIM, IN_DIM);
    if (e != cudaSuccess) {
        gemm_fp16_kernel<<<grid, 256, smem_bytes>>>(gx, gw, out, M, OUT_DIM, IN_DIM);
    }
}